// round 7
// baseline (speedup 1.0000x reference)
#include <cuda_runtime.h>
#include <cstdint>

#define IN_F  4096
#define OUT_F 16384
#define NB    8      // batch vectors
#define RPW   4      // rows per warp
#define WARPS 8
#define THREADS (WARPS * 32)          // 256
#define ROWS_PER_CTA (RPW * WARPS)    // 32
#define NCHUNK (IN_F / 128)           // 32 chunks of 128 cols
#define NSTAGE 4
#define DIST   (NSTAGE - 1)
#define STAGE_B (ROWS_PER_CTA * 128 * 4)   // 16384 bytes per stage
// smem layout: [0,2048) tab2 | [2048,2112) mbarriers | [4096, +4*16K) stages
#define SMEM_TAB2   0
#define SMEM_MBAR   2048
#define SMEM_STAGE  4096
#define SMEM_TOTAL  (SMEM_STAGE + NSTAGE * STAGE_B)   // 69632

__constant__ float NF4_CODE[16] = {
    -1.0f, -0.6961928009986877f, -0.5250730514526367f, -0.39491748809814453f,
    -0.28444138169288635f, -0.18477343022823334f, -0.09105003625154495f, 0.0f,
    0.07958029955625534f, 0.16093020141124725f, 0.24611230194568634f,
    0.33791524171829224f, 0.44070982933044434f, 0.5626170039176941f,
    0.7229568362236023f, 1.0f};

typedef unsigned long long ull;

__device__ __forceinline__ ull pk2(float lo, float hi) {
    ull r;
    asm("mov.b64 %0, {%1, %2};" : "=l"(r)
        : "r"(__float_as_uint(lo)), "r"(__float_as_uint(hi)));
    return r;
}
__device__ __forceinline__ void upk2(ull v, float& lo, float& hi) {
    unsigned int a, b;
    asm("mov.b64 {%0, %1}, %2;" : "=r"(a), "=r"(b) : "l"(v));
    lo = __uint_as_float(a); hi = __uint_as_float(b);
}
__device__ __forceinline__ void fma2(ull& acc, ull a, ull b) {
    asm("fma.rn.f32x2 %0, %1, %2, %0;" : "+l"(acc) : "l"(a), "l"(b));
}
__device__ __forceinline__ ull mul2(ull a, ull b) {
    ull r;
    asm("mul.rn.f32x2 %0, %1, %2;" : "=l"(r) : "l"(a), "l"(b));
    return r;
}

__device__ __forceinline__ void mbar_init(unsigned addr, unsigned count) {
    asm volatile("mbarrier.init.shared.b64 [%0], %1;" :: "r"(addr), "r"(count)
                 : "memory");
}
__device__ __forceinline__ void mbar_expect_tx(unsigned addr, unsigned bytes) {
    asm volatile("mbarrier.arrive.expect_tx.shared.b64 _, [%0], %1;"
                 :: "r"(addr), "r"(bytes) : "memory");
}
__device__ __forceinline__ void mbar_arrive(unsigned addr) {
    asm volatile("mbarrier.arrive.shared.b64 _, [%0];" :: "r"(addr) : "memory");
}
__device__ __forceinline__ void mbar_wait(unsigned addr, unsigned parity) {
    unsigned done;
    asm volatile(
        "{\n\t.reg .pred p;\n\t"
        "mbarrier.try_wait.parity.acquire.cta.shared::cta.b64 p, [%1], %2;\n\t"
        "selp.b32 %0, 1, 0, p;\n\t}"
        : "=r"(done) : "r"(addr), "r"(parity) : "memory");
    if (!done) {
        asm volatile(
            "{\n\t.reg .pred P1;\n\t"
            "WAIT_LOOP_%=:\n\t"
            "mbarrier.try_wait.parity.acquire.cta.shared::cta.b64 P1, [%0], %1, 0x989680;\n\t"
            "@P1 bra.uni WAIT_DONE_%=;\n\t"
            "bra.uni WAIT_LOOP_%=;\n\t"
            "WAIT_DONE_%=:\n\t}"
            :: "r"(addr), "r"(parity) : "memory");
    }
}
__device__ __forceinline__ void bulk_cp(unsigned dst, const void* src,
                                        unsigned bytes, unsigned mbar) {
    asm volatile(
        "cp.async.bulk.shared::cta.global.mbarrier::complete_tx::bytes "
        "[%0], [%1], %2, [%3];"
        :: "r"(dst), "l"(src), "r"(bytes), "r"(mbar) : "memory");
}

__global__ __launch_bounds__(THREADS, 2)
void nf4_qlinear_kernel(const float* __restrict__ x,
                        const int*   __restrict__ codes,
                        const float* __restrict__ absmax,
                        float*       __restrict__ out) {
    extern __shared__ char smem[];
    ull* tab2 = reinterpret_cast<ull*>(smem + SMEM_TAB2);
    const unsigned smem_u32 = (unsigned)__cvta_generic_to_shared(smem);
    const unsigned mb_full  = smem_u32 + SMEM_MBAR;        // 4 x 8B
    const unsigned mb_empty = smem_u32 + SMEM_MBAR + 32;   // 4 x 8B
    const unsigned stage_u  = smem_u32 + SMEM_STAGE;
    char* stage_g = smem + SMEM_STAGE;

    const int tid  = threadIdx.x;
    const int lane = tid & 31;
    const int warp = tid >> 5;

    // packed-pair NF4 table: tab2[c0*16+c1] = (nf4[c0], nf4[c1])
    for (int i = tid; i < 256; i += THREADS)
        tab2[i] = pk2(NF4_CODE[i >> 4], NF4_CODE[i & 15]);
    if (tid == 0) {
        #pragma unroll
        for (int s = 0; s < NSTAGE; ++s) {
            mbar_init(mb_full  + s * 8, 1);
            mbar_init(mb_empty + s * 8, WARPS);
        }
    }
    __syncthreads();

    const int rowCTA = blockIdx.x * ROWS_PER_CTA;
    const int row0   = rowCTA + warp * RPW;
    const int sel_hi = (lane >= 16);

    // ---- producer: warp 0, one bulk-copy per lane (32 rows x 512 B) ----
    auto produce = [&](int jj) {
        const int slot = jj & (NSTAGE - 1);
        const unsigned eph = (((unsigned)jj >> 2) + 1u) & 1u;  // cursor init phase 1
        mbar_wait(mb_empty + slot * 8, eph);
        if (lane == 0) mbar_expect_tx(mb_full + slot * 8, STAGE_B);
        __syncwarp();
        const char* src = reinterpret_cast<const char*>(
            codes + (size_t)(rowCTA + lane) * IN_F + jj * 128);
        bulk_cp(stage_u + slot * STAGE_B + lane * 512, src, 512,
                mb_full + slot * 8);
    };

    if (warp == 0) {
        #pragma unroll
        for (int s = 0; s < DIST; ++s) produce(s);
    }

    // acc[r][b] packs (even-col partial, odd-col partial)
    ull acc[RPW][NB];
    #pragma unroll
    for (int r = 0; r < RPW; ++r)
        #pragma unroll
        for (int b = 0; b < NB; ++b) acc[r][b] = 0ULL;

    #pragma unroll 1
    for (int j = 0; j < NCHUNK; ++j) {
        if (warp == 0 && j + DIST < NCHUNK) produce(j + DIST);

        const int slot = j & (NSTAGE - 1);
        mbar_wait(mb_full + slot * 8, ((unsigned)j >> 2) & 1u);

        const int col = j * 128 + lane * 4;
        // x column-pairs, already packed in memory: zero MOVs
        ull x01[NB], x23[NB];
        #pragma unroll
        for (int b = 0; b < NB; ++b) {
            const ulonglong2 xv = *reinterpret_cast<const ulonglong2*>(
                x + (size_t)b * IN_F + col);
            x01[b] = xv.x;
            x23[b] = xv.y;
        }

        const char* sb = stage_g + slot * STAGE_B;
        #pragma unroll
        for (int r = 0; r < RPW; ++r) {
            const int4 cv = *reinterpret_cast<const int4*>(
                sb + (warp * RPW + r) * 512 + lane * 16);
            const float a = __ldg(absmax + (size_t)(row0 + r) * (IN_F / 64)
                                  + j * 2 + sel_hi);
            const ull a2  = pk2(a, a);
            const ull w01 = mul2(tab2[cv.x * 16 + cv.y], a2);
            const ull w23 = mul2(tab2[cv.z * 16 + cv.w], a2);
            #pragma unroll
            for (int b = 0; b < NB; ++b) {
                fma2(acc[r][b], w01, x01[b]);
                fma2(acc[r][b], w23, x23[b]);
            }
        }

        __syncwarp();
        if (lane == 0) mbar_arrive(mb_empty + slot * 8);
    }

    // Reduce packed pairs, warp-reduce, store out[b, row]
    #pragma unroll
    for (int r = 0; r < RPW; ++r) {
        #pragma unroll
        for (int b = 0; b < NB; ++b) {
            float lo, hi;
            upk2(acc[r][b], lo, hi);
            float s = lo + hi;
            #pragma unroll
            for (int off = 16; off > 0; off >>= 1)
                s += __shfl_xor_sync(0xffffffffu, s, off);
            if (lane == 0) out[(size_t)b * OUT_F + row0 + r] = s;
        }
    }
}

extern "C" void kernel_launch(void* const* d_in, const int* in_sizes, int n_in,
                              void* d_out, int out_size) {
    const float* x      = (const float*)d_in[0];   // [8,1,4096] f32
    const int*   codes  = (const int*)d_in[1];     // [16384,4096] i32 (0..15)
    const float* absmax = (const float*)d_in[2];   // [16384,64] f32
    float*       out    = (float*)d_out;           // [8,1,16384] f32

    (void)in_sizes; (void)n_in; (void)out_size;
    static int configured = 0;
    if (!configured) {
        cudaFuncSetAttribute(nf4_qlinear_kernel,
                             cudaFuncAttributeMaxDynamicSharedMemorySize,
                             SMEM_TOTAL);
        configured = 1;
    }
    nf4_qlinear_kernel<<<OUT_F / ROWS_PER_CTA, THREADS, SMEM_TOTAL>>>(
        x, codes, absmax, out);
}

// round 9
// speedup vs baseline: 1.4519x; 1.4519x over previous
#include <cuda_runtime.h>
#include <cstdint>

#define IN_F  4096
#define OUT_F 16384
#define NB    8      // batch vectors
#define RPW   4      // rows per warp
#define WARPS 8
#define THREADS (WARPS * 32)          // 256
#define ROWS_PER_CTA (RPW * WARPS)    // 32
#define NCHUNK (IN_F / 128)           // 32 chunks (4 cols/lane each)

__constant__ float NF4_CODE[16] = {
    -1.0f, -0.6961928009986877f, -0.5250730514526367f, -0.39491748809814453f,
    -0.28444138169288635f, -0.18477343022823334f, -0.09105003625154495f, 0.0f,
    0.07958029955625534f, 0.16093020141124725f, 0.24611230194568634f,
    0.33791524171829224f, 0.44070982933044434f, 0.5626170039176941f,
    0.7229568362236023f, 1.0f};

typedef unsigned long long ull;

__device__ __forceinline__ ull pk2(float lo, float hi) {
    ull r;
    asm("mov.b64 %0, {%1, %2};" : "=l"(r)
        : "r"(__float_as_uint(lo)), "r"(__float_as_uint(hi)));
    return r;
}
__device__ __forceinline__ void upk2(ull v, float& lo, float& hi) {
    unsigned int a, b;
    asm("mov.b64 {%0, %1}, %2;" : "=r"(a), "=r"(b) : "l"(v));
    lo = __uint_as_float(a); hi = __uint_as_float(b);
}
__device__ __forceinline__ void fma2(ull& acc, ull a, ull b) {
    asm("fma.rn.f32x2 %0, %1, %2, %0;" : "+l"(acc) : "l"(a), "l"(b));
}
__device__ __forceinline__ ull mul2(ull a, ull b) {
    ull r;
    asm("mul.rn.f32x2 %0, %1, %2;" : "=l"(r) : "l"(a), "l"(b));
    return r;
}

__global__ __launch_bounds__(THREADS, 2)
void nf4_qlinear_kernel(const float* __restrict__ x,
                        const int*   __restrict__ codes,
                        const float* __restrict__ absmax,
                        float*       __restrict__ out) {
    // Packed-pair NF4 table: tab2[(c0<<4)|c1] = (nf4[c0], nf4[c1])
    __shared__ ull tab2[256];
    const int tid  = threadIdx.x;
    const int lane = tid & 31;
    const int warp = tid >> 5;
    for (int i = tid; i < 256; i += THREADS)
        tab2[i] = pk2(NF4_CODE[i >> 4], NF4_CODE[i & 15]);
    __syncthreads();

    const int row0   = blockIdx.x * ROWS_PER_CTA + warp * RPW;
    const int sel_hi = (lane >= 16);

    // Pointer-bump bases: all loads below use reg + compile-time-const offsets
    const int4*  cp = reinterpret_cast<const int4*>(
                          codes + (size_t)row0 * IN_F) + lane;   // +r*1024, +32/chunk
    const float* xp = x + lane * 4;                              // +b*IN_F, +128/chunk
    const float* ap = absmax + (size_t)row0 * (IN_F / 64) + sel_hi; // +r*64, +2/chunk

    // acc[r][b] packs (even-col, odd-col) partial dot products
    ull acc[RPW][NB];
    #pragma unroll
    for (int r = 0; r < RPW; ++r)
        #pragma unroll
        for (int b = 0; b < NB; ++b) acc[r][b] = 0ULL;

    #pragma unroll 1
    for (int j = 0; j < NCHUNK; ++j) {
        // ---- front-batched code burst: 4 independent LDG.128 ----
        int4 cv[RPW];
        #pragma unroll
        for (int r = 0; r < RPW; ++r) cv[r] = __ldcs(cp + r * (IN_F / 4));

        // ---- dequantize: one LDS.64 pair-lookup + one mul2 per column pair ----
        ull w01[RPW], w23[RPW];
        #pragma unroll
        for (int r = 0; r < RPW; ++r) {
            const float a  = __ldg(ap + r * (IN_F / 64));
            const ull   a2 = pk2(a, a);
            w01[r] = mul2(tab2[(cv[r].x << 4) | cv[r].y], a2);
            w23[r] = mul2(tab2[(cv[r].z << 4) | cv[r].w], a2);
        }

        // ---- x naturally packed as column pairs; FMA into all rows ----
        #pragma unroll
        for (int b = 0; b < NB; ++b) {
            const ulonglong2 xv = *reinterpret_cast<const ulonglong2*>(
                xp + (size_t)b * IN_F);
            #pragma unroll
            for (int r = 0; r < RPW; ++r) {
                fma2(acc[r][b], w01[r], xv.x);
                fma2(acc[r][b], w23[r], xv.y);
            }
        }

        cp += 32;    // 128 ints
        xp += 128;
        ap += 2;
    }

    // Reduce packed pairs, warp-reduce, store out[b, row]
    #pragma unroll
    for (int r = 0; r < RPW; ++r) {
        #pragma unroll
        for (int b = 0; b < NB; ++b) {
            float lo, hi;
            upk2(acc[r][b], lo, hi);
            float s = lo + hi;
            #pragma unroll
            for (int off = 16; off > 0; off >>= 1)
                s += __shfl_xor_sync(0xffffffffu, s, off);
            if (lane == 0) out[(size_t)b * OUT_F + row0 + r] = s;
        }
    }
}

extern "C" void kernel_launch(void* const* d_in, const int* in_sizes, int n_in,
                              void* d_out, int out_size) {
    const float* x      = (const float*)d_in[0];   // [8,1,4096] f32
    const int*   codes  = (const int*)d_in[1];     // [16384,4096] i32 (0..15)
    const float* absmax = (const float*)d_in[2];   // [16384,64] f32
    float*       out    = (float*)d_out;           // [8,1,16384] f32

    (void)in_sizes; (void)n_in; (void)out_size;
    nf4_qlinear_kernel<<<OUT_F / ROWS_PER_CTA, THREADS>>>(x, codes, absmax, out);
}